// round 6
// baseline (speedup 1.0000x reference)
#include <cuda_runtime.h>
#include <cstdint>

// LengthRegulator: expand hidden_phonems [B,L,D] by durations [B,L] into
// out [B, max_T, D], zero-padded beyond totals[b].
//
// R6: TMA bulk-store replication. Each block (256 thr, 4 phonemes):
//  1. packed block-reduction over the batch's 512 durations -> (total, prefix)
//  2. loads its 4 rows (coalesced LDG.128, L2-resident), replicates them into
//     a contiguous SMEM staging buffer (STS.128, conflict-free, ~4cyc issue)
//  3. ONE elected cp.async.bulk shared->global of the whole run (avg ~14KB)
//     -- replication leaves the LSU/L1 store path entirely (R5 cap).
//  4. strided STG zeroing of the padding tail (tiny).

#define B_CONST 32
#define L_CONST 512
#define D_CONST 256
#define D4 (D_CONST / 4)
#define MAX_DUR 8
#define P_PER_BLK 4
#define BLOCKS_PER_BATCH (L_CONST / P_PER_BLK)     // 128
#define MAX_FRAMES (P_PER_BLK * (MAX_DUR - 1))     // 28

__device__ __forceinline__ uint32_t smem_u32(const void* p) {
    uint32_t a;
    asm("{ .reg .u64 tmp; cvta.to.shared.u64 tmp, %1; cvt.u32.u64 %0, tmp; }"
        : "=r"(a) : "l"(p));
    return a;
}

__global__ void __launch_bounds__(256) lr_fused(
    const float4* __restrict__ hidden4,
    const int*    __restrict__ durations,
    float4*       __restrict__ out4,
    int max_T)
{
    __shared__ float4 stage[MAX_FRAMES * D4];   // 28 KB contiguous frame run
    __shared__ int wred[8];
    __shared__ int s_res;

    const int t        = threadIdx.x;           // 0..255
    const int blk      = blockIdx.x;            // 0..4095
    const int b        = blk >> 7;              // batch
    const int blkLocal = blk & (BLOCKS_PER_BATCH - 1);
    const int l0       = blkLocal * P_PER_BLK;  // first phoneme (multiple of 4)

    const int* __restrict__ dbat = durations + b * L_CONST;

    // ---- packed reduction: low 16 = batch total, high 16 = prefix(l0)
    int2 dd = ((const int2*)dbat)[t];
    int full = dd.x + dd.y;
    int packed = full + (((2 * t < l0) ? full : 0) << 16);

    #pragma unroll
    for (int o = 16; o > 0; o >>= 1)
        packed += __shfl_down_sync(0xffffffffu, packed, o);

    if ((t & 31) == 0) wred[t >> 5] = packed;
    __syncthreads();

    if (t < 8) {
        int p = wred[t];
        #pragma unroll
        for (int o = 4; o > 0; o >>= 1)
            p += __shfl_down_sync(0x000000ffu, p, o);
        if (t == 0) s_res = p;
    }
    __syncthreads();

    const int total  = s_res & 0xFFFF;
    const int prefix = s_res >> 16;             // exclusive prefix at l0

    // ---- block-local durations (warp-uniform L1-hit scalar loads)
    const int fgrp = t >> 6;                    // phoneme within block [0,4)
    const int lane = t & 63;                    // float4 lane over D
    const int d0 = dbat[l0], d1 = dbat[l0 + 1], d2 = dbat[l0 + 2], d3 = dbat[l0 + 3];
    const int nFrames = d0 + d1 + d2 + d3;

    int sLoc = 0;                               // local frame offset of my phoneme
    if (fgrp > 0) sLoc += d0;
    if (fgrp > 1) sLoc += d1;
    if (fgrp > 2) sLoc += d2;
    const int d = (fgrp == 0) ? d0 : (fgrp == 1) ? d1 : (fgrp == 2) ? d2 : d3;

    // ---- load row, replicate into contiguous SMEM staging (STS.128)
    const float4 v = hidden4[((size_t)b * L_CONST + l0 + fgrp) * D4 + lane];
    for (int j = 0; j < d; ++j)                 // d warp-uniform -> no divergence
        stage[(sLoc + j) * D4 + lane] = v;
    __syncthreads();

    // ---- single bulk store of the whole run: SMEM -> out[b, prefix ...]
    if (t == 0 && nFrames > 0) {
        asm volatile("fence.proxy.async.shared::cta;" ::: "memory");
        const char* gdst = (const char*)(out4 + ((size_t)b * max_T + prefix) * D4);
        const uint32_t ssrc = smem_u32(stage);
        const uint32_t bytes = (uint32_t)nFrames * (D_CONST * 4);
        asm volatile(
            "cp.async.bulk.global.shared::cta.bulk_group [%0], [%1], %2;"
            :: "l"(gdst), "r"(ssrc), "r"(bytes) : "memory");
        asm volatile("cp.async.bulk.commit_group;" ::: "memory");
    }

    // ---- tail zeroing: this block's strided share of [total, max_T)
    const float4 zero = make_float4(0.f, 0.f, 0.f, 0.f);
    for (int f = total + blkLocal * 4 + fgrp; f < max_T; f += 4 * BLOCKS_PER_BATCH) {
        out4[((size_t)b * max_T + f) * D4 + lane] = zero;
    }

    // ---- drain the bulk store before exit
    if (t == 0 && nFrames > 0) {
        asm volatile("cp.async.bulk.wait_group 0;" ::: "memory");
    }
}

extern "C" void kernel_launch(void* const* d_in, const int* in_sizes, int n_in,
                              void* d_out, int out_size) {
    const float* hidden    = (const float*)d_in[0];   // [B, L, D] fp32
    const int*   durations = (const int*)d_in[1];     // [B, L] int32
    float*       out       = (float*)d_out;

    const int max_T = out_size / (B_CONST * D_CONST);

    lr_fused<<<B_CONST * BLOCKS_PER_BATCH, 256>>>(
        (const float4*)hidden, durations, (float4*)out, max_T);
}